// round 1
// baseline (speedup 1.0000x reference)
#include <cuda_runtime.h>
#include <cuda_bf16.h>
#include <cstdint>

// Problem constants
#define B_TOT 2048
#define S_LEN 512
#define H_DIM 256
#define C_DIM 10
#define TB    16    // batch columns per CTA -> 2048/16 = 128 CTAs

// Device scratch (no allocations allowed in kernel_launch)
__device__ float g_xT[S_LEN * B_TOT];          // xT[t*B + b]
__device__ float g_Wt[H_DIM * H_DIM];          // packed: [(k4*H + i)*4 + j] = W_hh[i][4*k4 + j]

// ---------------------------------------------------------------------------
// x transpose: x[B][S] -> xT[S][B], tiled for coalescing both sides
// ---------------------------------------------------------------------------
__global__ void transpose_x_kernel(const float* __restrict__ x) {
    __shared__ float tile[32][33];
    int t0 = blockIdx.x * 32;
    int b0 = blockIdx.y * 32;
    int tx = threadIdx.x, ty = threadIdx.y;
    tile[ty][tx] = x[(b0 + ty) * S_LEN + t0 + tx];
    __syncthreads();
    g_xT[(t0 + ty) * B_TOT + b0 + tx] = tile[tx][ty];
}

// ---------------------------------------------------------------------------
// W_hh repack: row-major [i][k] -> [(k4*H + i)*4 + j] so that per-thread
// per-k4 weight fetch is a single coalesced LDG.128 across threads (tid = i).
// ---------------------------------------------------------------------------
__global__ void repack_w_kernel(const float* __restrict__ W) {
    int o = blockIdx.x * blockDim.x + threadIdx.x;   // 0 .. H*H/4-1
    if (o >= H_DIM * H_DIM / 4) return;
    int k4 = o >> 8;          // o / 256
    int i  = o & 255;         // o % 256
    float4 v = *(const float4*)&W[i * H_DIM + k4 * 4];
    ((float4*)g_Wt)[o] = v;
}

// ---------------------------------------------------------------------------
// Main recurrent kernel. One CTA owns TB batch columns for all 512 steps.
// Thread tid = hidden row i. h tile lives in smem as hs[b][k].
// Inner product uses packed fma.rn.f32x2 (pairs over k) to double fp32 rate.
// ---------------------------------------------------------------------------
__global__ void __launch_bounds__(256, 1) rnn_main_kernel(
    const float* __restrict__ W_hx,
    const float* __restrict__ b_h,
    const float* __restrict__ W_ph,
    const float* __restrict__ b_p,
    float* __restrict__ out)
{
    __shared__ __align__(16) float hs[TB][H_DIM];   // hs[b][k]
    __shared__ float xs[TB];

    const int tid = threadIdx.x;          // hidden row index i
    const int b0  = blockIdx.x * TB;

    const float wx   = W_hx[tid];
    const float bias = b_h[tid];

    // h0 = 0
    #pragma unroll
    for (int b = 0; b < TB; b++) hs[b][tid] = 0.0f;
    __syncthreads();

    const float4* __restrict__ Wp = ((const float4*)g_Wt) + tid;  // Wp[k4*H]

    for (int t = 0; t < S_LEN; t++) {
        // Stage this step's x values (TB floats)
        if (tid < TB) xs[tid] = g_xT[t * B_TOT + b0 + tid];
        __syncthreads();   // also publishes previous step's hs writes

        // acc[b] packed as f32x2: lo accumulates even-k partials, hi odd-k.
        unsigned long long acc[TB];
        #pragma unroll
        for (int b = 0; b < TB; b++) {
            float v = fmaf(wx, xs[b], bias);
            unsigned lo = __float_as_uint(v);
            acc[b] = (unsigned long long)lo;      // hi lane = 0.0f
        }

        #pragma unroll 4
        for (int k4 = 0; k4 < H_DIM / 4; k4++) {
            float4 w4 = Wp[k4 * H_DIM];           // coalesced LDG.128
            unsigned long long w01, w23;
            asm("mov.b64 %0, {%1, %2};" : "=l"(w01) : "f"(w4.x), "f"(w4.y));
            asm("mov.b64 %0, {%1, %2};" : "=l"(w23) : "f"(w4.z), "f"(w4.w));
            #pragma unroll
            for (int b = 0; b < TB; b++) {
                // broadcast LDS.128: all lanes read the same 16B of hs[b]
                ulonglong2 hp = *(const ulonglong2*)&hs[b][k4 * 4];
                asm("fma.rn.f32x2 %0, %1, %2, %0;" : "+l"(acc[b]) : "l"(w01), "l"(hp.x));
                asm("fma.rn.f32x2 %0, %1, %2, %0;" : "+l"(acc[b]) : "l"(w23), "l"(hp.y));
            }
        }

        __syncthreads();   // all reads of hs done before overwrite

        #pragma unroll
        for (int b = 0; b < TB; b++) {
            float lo = __uint_as_float((unsigned)(acc[b] & 0xffffffffULL));
            float hi = __uint_as_float((unsigned)(acc[b] >> 32));
            float z  = lo + hi;
            // tanh(z) = 1 - 2/(exp(2z)+1); saturates correctly at +/-inf
            float e  = __expf(2.0f * z);
            float th = 1.0f - __fdividef(2.0f, e + 1.0f);
            hs[b][tid] = th;
        }
        // next iteration's first __syncthreads publishes these writes
    }
    __syncthreads();

    // Final projection: out[b][c] = sum_i W_ph[c][i] * h[i][b] + b_p[c]
    if (tid < TB * C_DIM) {
        int b = tid / C_DIM;
        int c = tid % C_DIM;
        float s = b_p[c];
        const float4* wph = (const float4*)(W_ph + c * H_DIM);
        const float4* hv  = (const float4*)&hs[b][0];
        #pragma unroll 8
        for (int q = 0; q < H_DIM / 4; q++) {
            float4 a  = wph[q];
            float4 hh = hv[q];
            s += a.x * hh.x + a.y * hh.y + a.z * hh.z + a.w * hh.w;
        }
        out[(b0 + b) * C_DIM + c] = s;
    }
}

// ---------------------------------------------------------------------------
// kernel_launch: graph-capturable, allocation-free
// Inputs (metadata order): x, W_hx, W_hh, b_h, W_ph, b_p
// ---------------------------------------------------------------------------
extern "C" void kernel_launch(void* const* d_in, const int* in_sizes, int n_in,
                              void* d_out, int out_size) {
    const float* x    = (const float*)d_in[0];
    const float* W_hx = (const float*)d_in[1];
    const float* W_hh = (const float*)d_in[2];
    const float* b_h  = (const float*)d_in[3];
    const float* W_ph = (const float*)d_in[4];
    const float* b_p  = (const float*)d_in[5];
    float* out = (float*)d_out;

    // 1) transpose x -> xT[t][b]
    dim3 tgrid(S_LEN / 32, B_TOT / 32);
    dim3 tblk(32, 32);
    transpose_x_kernel<<<tgrid, tblk>>>(x);

    // 2) repack W_hh
    int total4 = H_DIM * H_DIM / 4;           // 16384
    repack_w_kernel<<<(total4 + 255) / 256, 256>>>(W_hh);

    // 3) run the recurrence + projection
    rnn_main_kernel<<<B_TOT / TB, 256>>>(W_hx, b_h, W_ph, b_p, out);
}

// round 2
// speedup vs baseline: 1.0033x; 1.0033x over previous
#include <cuda_runtime.h>
#include <cuda_bf16.h>
#include <cstdint>

// Problem constants
#define B_TOT 2048
#define S_LEN 512
#define H_DIM 256
#define C_DIM 10
#define TB    16    // batch columns per CTA -> 2048/16 = 128 CTAs

// Device scratch (no allocations allowed in kernel_launch)
__device__ float g_xT[S_LEN * B_TOT];          // xT[t*B + b]
__device__ float g_Wt[H_DIM * H_DIM];          // packed: [(k4*H + i)*4 + j] = W_hh[i][4*k4 + j]

// ---------------------------------------------------------------------------
// x transpose: x[B][S] -> xT[S][B], tiled for coalescing both sides
// ---------------------------------------------------------------------------
__global__ void transpose_x_kernel(const float* __restrict__ x) {
    __shared__ float tile[32][33];
    int t0 = blockIdx.x * 32;
    int b0 = blockIdx.y * 32;
    int tx = threadIdx.x, ty = threadIdx.y;
    tile[ty][tx] = x[(b0 + ty) * S_LEN + t0 + tx];
    __syncthreads();
    g_xT[(t0 + ty) * B_TOT + b0 + tx] = tile[tx][ty];
}

// ---------------------------------------------------------------------------
// W_hh repack: row-major [i][k] -> [(k4*H + i)*4 + j] so that per-thread
// per-k4 weight fetch is a single coalesced LDG.128 across threads (tid = i).
// ---------------------------------------------------------------------------
__global__ void repack_w_kernel(const float* __restrict__ W) {
    int o = blockIdx.x * blockDim.x + threadIdx.x;   // 0 .. H*H/4-1
    if (o >= H_DIM * H_DIM / 4) return;
    int k4 = o >> 8;          // o / 256
    int i  = o & 255;         // o % 256
    float4 v = *(const float4*)&W[i * H_DIM + k4 * 4];
    ((float4*)g_Wt)[o] = v;
}

// ---------------------------------------------------------------------------
// Main recurrent kernel. One CTA owns TB batch columns for all 512 steps.
// Thread tid = hidden row i. h tile lives in smem as hs[b][k].
// Inner product uses packed fma.rn.f32x2 (pairs over k) to double fp32 rate.
// ---------------------------------------------------------------------------
__global__ void __launch_bounds__(256, 1) rnn_main_kernel(
    const float* __restrict__ W_hx,
    const float* __restrict__ b_h,
    const float* __restrict__ W_ph,
    const float* __restrict__ b_p,
    float* __restrict__ out)
{
    __shared__ __align__(16) float hs[TB][H_DIM];   // hs[b][k]
    __shared__ float xs[TB];

    const int tid = threadIdx.x;          // hidden row index i
    const int b0  = blockIdx.x * TB;

    const float wx   = W_hx[tid];
    const float bias = b_h[tid];

    // h0 = 0
    #pragma unroll
    for (int b = 0; b < TB; b++) hs[b][tid] = 0.0f;
    __syncthreads();

    const float4* __restrict__ Wp = ((const float4*)g_Wt) + tid;  // Wp[k4*H]

    for (int t = 0; t < S_LEN; t++) {
        // Stage this step's x values (TB floats)
        if (tid < TB) xs[tid] = g_xT[t * B_TOT + b0 + tid];
        __syncthreads();   // also publishes previous step's hs writes

        // acc[b] packed as f32x2: lo accumulates even-k partials, hi odd-k.
        unsigned long long acc[TB];
        #pragma unroll
        for (int b = 0; b < TB; b++) {
            float v = fmaf(wx, xs[b], bias);
            unsigned lo = __float_as_uint(v);
            acc[b] = (unsigned long long)lo;      // hi lane = 0.0f
        }

        #pragma unroll 4
        for (int k4 = 0; k4 < H_DIM / 4; k4++) {
            float4 w4 = Wp[k4 * H_DIM];           // coalesced LDG.128
            unsigned long long w01, w23;
            asm("mov.b64 %0, {%1, %2};" : "=l"(w01) : "f"(w4.x), "f"(w4.y));
            asm("mov.b64 %0, {%1, %2};" : "=l"(w23) : "f"(w4.z), "f"(w4.w));
            #pragma unroll
            for (int b = 0; b < TB; b++) {
                // broadcast LDS.128: all lanes read the same 16B of hs[b]
                ulonglong2 hp = *(const ulonglong2*)&hs[b][k4 * 4];
                asm("fma.rn.f32x2 %0, %1, %2, %0;" : "+l"(acc[b]) : "l"(w01), "l"(hp.x));
                asm("fma.rn.f32x2 %0, %1, %2, %0;" : "+l"(acc[b]) : "l"(w23), "l"(hp.y));
            }
        }

        __syncthreads();   // all reads of hs done before overwrite

        #pragma unroll
        for (int b = 0; b < TB; b++) {
            float lo = __uint_as_float((unsigned)(acc[b] & 0xffffffffULL));
            float hi = __uint_as_float((unsigned)(acc[b] >> 32));
            float z  = lo + hi;
            // tanh(z) = 1 - 2/(exp(2z)+1); saturates correctly at +/-inf
            float e  = __expf(2.0f * z);
            float th = 1.0f - __fdividef(2.0f, e + 1.0f);
            hs[b][tid] = th;
        }
        // next iteration's first __syncthreads publishes these writes
    }
    __syncthreads();

    // Final projection: out[b][c] = sum_i W_ph[c][i] * h[i][b] + b_p[c]
    if (tid < TB * C_DIM) {
        int b = tid / C_DIM;
        int c = tid % C_DIM;
        float s = b_p[c];
        const float4* wph = (const float4*)(W_ph + c * H_DIM);
        const float4* hv  = (const float4*)&hs[b][0];
        #pragma unroll 8
        for (int q = 0; q < H_DIM / 4; q++) {
            float4 a  = wph[q];
            float4 hh = hv[q];
            s += a.x * hh.x + a.y * hh.y + a.z * hh.z + a.w * hh.w;
        }
        out[(b0 + b) * C_DIM + c] = s;
    }
}

// ---------------------------------------------------------------------------
// kernel_launch: graph-capturable, allocation-free
// Inputs (metadata order): x, W_hx, W_hh, b_h, W_ph, b_p
// ---------------------------------------------------------------------------
extern "C" void kernel_launch(void* const* d_in, const int* in_sizes, int n_in,
                              void* d_out, int out_size) {
    const float* x    = (const float*)d_in[0];
    const float* W_hx = (const float*)d_in[1];
    const float* W_hh = (const float*)d_in[2];
    const float* b_h  = (const float*)d_in[3];
    const float* W_ph = (const float*)d_in[4];
    const float* b_p  = (const float*)d_in[5];
    float* out = (float*)d_out;

    // 1) transpose x -> xT[t][b]
    dim3 tgrid(S_LEN / 32, B_TOT / 32);
    dim3 tblk(32, 32);
    transpose_x_kernel<<<tgrid, tblk>>>(x);

    // 2) repack W_hh
    int total4 = H_DIM * H_DIM / 4;           // 16384
    repack_w_kernel<<<(total4 + 255) / 256, 256>>>(W_hh);

    // 3) run the recurrence + projection
    rnn_main_kernel<<<B_TOT / TB, 256>>>(W_hx, b_h, W_ph, b_p, out);
}

// round 7
// speedup vs baseline: 4.7130x; 4.6975x over previous
#include <cuda_runtime.h>
#include <cuda_bf16.h>
#include <cstdint>

// Problem constants
#define B_TOT 2048
#define S_LEN 512
#define H_DIM 256
#define C_DIM 10
#define NB    16                 // batch columns per CTA
#define NCTA  (B_TOT / NB)       // 128 CTAs

// ---- SMEM layout (bytes, dynamic) -----------------------------------------
// W_hi packed in mma-fragment order: 128 KB
// h buffers: 2 x (hi 8KB + lo 8KB) = 32 KB   (layout [k][n] bf16, row = 32 B)
// x tile [b][t] fp32: 32 KB
// final h fp32 [b][k]: 16 KB
#define SM_WPK   0
#define SM_H     131072
#define SM_XS    (SM_H + 32768)
#define SM_HF32  (SM_XS + 32768)
#define SM_TOTAL (SM_HF32 + 16384)     // 212992 bytes

// ---------------------------------------------------------------------------
// helpers
// ---------------------------------------------------------------------------
__device__ __forceinline__ uint32_t smem_u32(const void* p) {
    uint32_t a;
    asm("{ .reg .u64 t; cvta.to.shared.u64 t, %1; cvt.u32.u64 %0, t; }" : "=r"(a) : "l"(p));
    return a;
}
__device__ __forceinline__ uint32_t pack_bf16x2(float a, float b) {
    __nv_bfloat162 t = __floats2bfloat162_rn(a, b);
    return *reinterpret_cast<uint32_t*>(&t);
}
// residual (lo part) of a float2 against its packed bf16x2 hi part
__device__ __forceinline__ uint32_t pack_lo(float2 v, uint32_t hi) {
    __nv_bfloat162 hh = *reinterpret_cast<__nv_bfloat162*>(&hi);
    return pack_bf16x2(v.x - __bfloat162float(hh.x), v.y - __bfloat162float(hh.y));
}
__device__ __forceinline__ float tanh_fast(float z) {
    float e = __expf(2.0f * z);
    return 1.0f - __fdividef(2.0f, e + 1.0f);
}

// mma.sync m16n8k16 row.col f32.bf16.bf16.f32 (sm_80+; HMMA on Blackwell)
__device__ __forceinline__ void mma_bf16(float c[4],
                                         uint32_t a0, uint32_t a1, uint32_t a2, uint32_t a3,
                                         uint32_t b0, uint32_t b1) {
    asm("mma.sync.aligned.m16n8k16.row.col.f32.bf16.bf16.f32 "
        "{%0,%1,%2,%3}, {%4,%5,%6,%7}, {%8,%9}, {%0,%1,%2,%3};"
        : "+f"(c[0]), "+f"(c[1]), "+f"(c[2]), "+f"(c[3])
        : "r"(a0), "r"(a1), "r"(a2), "r"(a3), "r"(b0), "r"(b1));
}
// ldmatrix x4 transposed b16 (sm_75+)
__device__ __forceinline__ void ldsm_x4_trans(uint32_t d[4], uint32_t addr) {
    asm volatile("ldmatrix.sync.aligned.m8n8.x4.trans.shared.b16 {%0,%1,%2,%3}, [%4];"
                 : "=r"(d[0]), "=r"(d[1]), "=r"(d[2]), "=r"(d[3]) : "r"(addr));
}

// ---------------------------------------------------------------------------
// Main kernel: one CTA owns NB=16 batch columns for all 512 steps.
// 8 warps; warp w owns hidden rows [32w, 32w+32) (two m16 tiles).
// 3-pass bf16-split fp32 emulation: W_hi@h_hi + W_hi@h_lo + W_lo@h_hi.
// ---------------------------------------------------------------------------
__global__ void __launch_bounds__(256, 1) rnn_mma_kernel(
    const float* __restrict__ x,
    const float* __restrict__ W_hx,
    const float* __restrict__ W_hh,
    const float* __restrict__ b_h,
    const float* __restrict__ W_ph,
    const float* __restrict__ b_p,
    float* __restrict__ out)
{
    extern __shared__ __align__(1024) char smem[];
    const uint32_t sbase = smem_u32(smem);
    const int tid  = threadIdx.x;
    const int wid  = tid >> 5;
    const int lane = tid & 31;
    const int g    = lane >> 2;       // fragment group (row within 8)
    const int t2   = lane & 3;        // thread-in-group (col pair / k pair)
    const int b0g  = blockIdx.x * NB;

    // W_lo A-fragments, register resident: [mtile][kstep][4 regs]
    uint32_t wlo[2][16][4];

    // --- Prologue: pack W_hi -> SMEM fragments, W_lo -> registers ----------
    #pragma unroll
    for (int mt = 0; mt < 2; mt++) {
        const int r0 = wid * 32 + mt * 16 + g;
        const int r1 = r0 + 8;
        #pragma unroll
        for (int ks = 0; ks < 16; ks++) {
            const int c0 = ks * 16 + t2 * 2;
            float2 v00 = *(const float2*)&W_hh[r0 * H_DIM + c0];
            float2 v10 = *(const float2*)&W_hh[r1 * H_DIM + c0];
            float2 v01 = *(const float2*)&W_hh[r0 * H_DIM + c0 + 8];
            float2 v11 = *(const float2*)&W_hh[r1 * H_DIM + c0 + 8];
            uint32_t h0 = pack_bf16x2(v00.x, v00.y);
            uint32_t h1 = pack_bf16x2(v10.x, v10.y);
            uint32_t h2 = pack_bf16x2(v01.x, v01.y);
            uint32_t h3 = pack_bf16x2(v11.x, v11.y);
            wlo[mt][ks][0] = pack_lo(v00, h0);
            wlo[mt][ks][1] = pack_lo(v10, h1);
            wlo[mt][ks][2] = pack_lo(v01, h2);
            wlo[mt][ks][3] = pack_lo(v11, h3);
            *(uint4*)(smem + SM_WPK + ((((wid * 2 + mt) * 16 + ks) * 32 + lane) * 16)) =
                make_uint4(h0, h1, h2, h3);
        }
    }
    // --- Prologue: x tile -> SMEM [b][t] fp32 ------------------------------
    {
        const float4* x4 = (const float4*)x;
        #pragma unroll
        for (int it = 0; it < 8; it++) {
            int idx4 = tid + it * 256;            // over 2048 float4
            int b  = idx4 >> 7;
            int t4 = idx4 & 127;
            float4 v = x4[(size_t)(b0g + b) * (S_LEN / 4) + t4];
            *(float4*)(smem + SM_XS + ((size_t)b * S_LEN + t4 * 4) * 4) = v;
        }
    }
    // --- Per-row wx/bias for this thread's 4 rows --------------------------
    float wxr[4], bsr[4];
    #pragma unroll
    for (int j = 0; j < 4; j++) {
        int r = wid * 32 + j * 8 + g;            // rows g, g+8, g+16, g+24 (+32w)
        wxr[j] = W_hx[r];
        bsr[j] = b_h[r];
    }
    const float wx0 = W_hx[tid];
    const float bh0 = b_h[tid];

    __syncthreads();   // publish W_hi pack + x tile

    // --- Step 0: h^1 = tanh(wx * x[.,0] + bias), h0 = 0; write buf 1 -------
    {
        char* hw = smem + SM_H + 1 * 16384;      // buf 1 (hi), +8192 lo
        #pragma unroll
        for (int b = 0; b < NB; b += 2) {
            float x0 = *(const float*)(smem + SM_XS + ((size_t)b * S_LEN) * 4);
            float x1 = *(const float*)(smem + SM_XS + ((size_t)(b + 1) * S_LEN) * 4);
            float th0 = tanh_fast(fmaf(wx0, x0, bh0));
            float th1 = tanh_fast(fmaf(wx0, x1, bh0));
            uint32_t hp = pack_bf16x2(th0, th1);
            float2 vv; vv.x = th0; vv.y = th1;
            uint32_t lp = pack_lo(vv, hp);
            *(uint32_t*)(hw + tid * 32 + b * 2)        = hp;
            *(uint32_t*)(hw + 8192 + tid * 32 + b * 2) = lp;
        }
    }
    __syncthreads();

    // ldmatrix per-lane row offset inside an h tile (x4.trans):
    // lanes 0-15 -> rows 0-15 / n-cols 0-7 (matrices 0,1);
    // lanes 16-31 -> rows 0-15 / n-cols 8-15 (matrices 2,3).
    const uint32_t roff = (lane < 16) ? (uint32_t)lane * 32u
                                      : (uint32_t)(lane - 16) * 32u + 16u;
    // Pre-biased read bases for the two h double-buffers (hoisted out of loop)
    const uint32_t hrd0 = sbase + SM_H + roff;            // buffer 0
    const uint32_t hrd1 = hrd0 + 16384u;                  // buffer 1
    const char* wbase = smem + SM_WPK + (size_t)(wid * 2) * 16 * 512 + (size_t)lane * 16;

    // --- Main recurrence: t = 1..511 ---------------------------------------
    for (int t = 1; t < S_LEN; t++) {
        const uint32_t hhird = (t & 1) ? hrd1 : hrd0;     // read h^t
        const uint32_t hlord = hhird + 8192u;
        char* hwhi = smem + SM_H + ((t + 1) & 1) * 16384; // write h^{t+1}
        char* hwlo = hwhi + 8192;

        float c[2][2][4];
        #pragma unroll
        for (int mi = 0; mi < 2; mi++)
            #pragma unroll
            for (int ni = 0; ni < 2; ni++)
                #pragma unroll
                for (int q = 0; q < 4; q++) c[mi][ni][q] = 0.0f;

        #pragma unroll
        for (int ks = 0; ks < 16; ks++) {
            uint4 a0 = *(const uint4*)(wbase + ks * 512);          // W_hi, m-tile 0
            uint4 a1 = *(const uint4*)(wbase + 8192 + ks * 512);   // W_hi, m-tile 1
            uint32_t bh[4], bl[4];
            ldsm_x4_trans(bh, hhird + (uint32_t)ks * 512u);
            ldsm_x4_trans(bl, hlord + (uint32_t)ks * 512u);

            // pass 1: W_hi @ h_hi
            mma_bf16(c[0][0], a0.x, a0.y, a0.z, a0.w, bh[0], bh[1]);
            mma_bf16(c[0][1], a0.x, a0.y, a0.z, a0.w, bh[2], bh[3]);
            mma_bf16(c[1][0], a1.x, a1.y, a1.z, a1.w, bh[0], bh[1]);
            mma_bf16(c[1][1], a1.x, a1.y, a1.z, a1.w, bh[2], bh[3]);
            // pass 2: W_hi @ h_lo
            mma_bf16(c[0][0], a0.x, a0.y, a0.z, a0.w, bl[0], bl[1]);
            mma_bf16(c[0][1], a0.x, a0.y, a0.z, a0.w, bl[2], bl[3]);
            mma_bf16(c[1][0], a1.x, a1.y, a1.z, a1.w, bl[0], bl[1]);
            mma_bf16(c[1][1], a1.x, a1.y, a1.z, a1.w, bl[2], bl[3]);
            // pass 3: W_lo @ h_hi  (A from registers)
            mma_bf16(c[0][0], wlo[0][ks][0], wlo[0][ks][1], wlo[0][ks][2], wlo[0][ks][3], bh[0], bh[1]);
            mma_bf16(c[0][1], wlo[0][ks][0], wlo[0][ks][1], wlo[0][ks][2], wlo[0][ks][3], bh[2], bh[3]);
            mma_bf16(c[1][0], wlo[1][ks][0], wlo[1][ks][1], wlo[1][ks][2], wlo[1][ks][3], bh[0], bh[1]);
            mma_bf16(c[1][1], wlo[1][ks][0], wlo[1][ks][1], wlo[1][ks][2], wlo[1][ks][3], bh[2], bh[3]);
        }

        // epilogue: z = C + wx*x + bias -> tanh -> split -> store
        float xv[4];
        #pragma unroll
        for (int ni = 0; ni < 2; ni++) {
            int b = ni * 8 + t2 * 2;
            xv[ni * 2 + 0] = *(const float*)(smem + SM_XS + ((size_t)b * S_LEN + t) * 4);
            xv[ni * 2 + 1] = *(const float*)(smem + SM_XS + ((size_t)(b + 1) * S_LEN + t) * 4);
        }

        if (t < S_LEN - 1) {
            #pragma unroll
            for (int mi = 0; mi < 2; mi++) {
                #pragma unroll
                for (int half = 0; half < 2; half++) {
                    int row = wid * 32 + mi * 16 + half * 8 + g;
                    float wxv = wxr[mi * 2 + half];
                    float bsv = bsr[mi * 2 + half];
                    #pragma unroll
                    for (int ni = 0; ni < 2; ni++) {
                        int bcol = ni * 8 + t2 * 2;
                        float z0 = c[mi][ni][half * 2 + 0] + fmaf(wxv, xv[ni * 2 + 0], bsv);
                        float z1 = c[mi][ni][half * 2 + 1] + fmaf(wxv, xv[ni * 2 + 1], bsv);
                        float th0 = tanh_fast(z0);
                        float th1 = tanh_fast(z1);
                        uint32_t hp = pack_bf16x2(th0, th1);
                        float2 vv; vv.x = th0; vv.y = th1;
                        uint32_t lp = pack_lo(vv, hp);
                        *(uint32_t*)(hwhi + row * 32 + bcol * 2) = hp;
                        *(uint32_t*)(hwlo + row * 32 + bcol * 2) = lp;
                    }
                }
            }
        } else {
            // final step: store h^512 as fp32 [b][k]
            #pragma unroll
            for (int mi = 0; mi < 2; mi++) {
                #pragma unroll
                for (int half = 0; half < 2; half++) {
                    int row = wid * 32 + mi * 16 + half * 8 + g;
                    float wxv = wxr[mi * 2 + half];
                    float bsv = bsr[mi * 2 + half];
                    #pragma unroll
                    for (int ni = 0; ni < 2; ni++) {
                        int bcol = ni * 8 + t2 * 2;
                        float z0 = c[mi][ni][half * 2 + 0] + fmaf(wxv, xv[ni * 2 + 0], bsv);
                        float z1 = c[mi][ni][half * 2 + 1] + fmaf(wxv, xv[ni * 2 + 1], bsv);
                        *(float*)(smem + SM_HF32 + ((size_t)bcol * H_DIM + row) * 4)       = tanh_fast(z0);
                        *(float*)(smem + SM_HF32 + ((size_t)(bcol + 1) * H_DIM + row) * 4) = tanh_fast(z1);
                    }
                }
            }
        }
        __syncthreads();
    }

    // --- Final projection: out[b][c] = sum_i W_ph[c][i] * h[i][b] + b_p[c] --
    if (tid < NB * C_DIM) {
        int b = tid / C_DIM;
        int c = tid % C_DIM;
        float s = b_p[c];
        const float4* wph = (const float4*)(W_ph + c * H_DIM);
        const float4* hv  = (const float4*)(smem + SM_HF32 + (size_t)b * H_DIM * 4);
        #pragma unroll 8
        for (int q = 0; q < H_DIM / 4; q++) {
            float4 a  = wph[q];
            float4 hh = hv[q];
            s += a.x * hh.x + a.y * hh.y + a.z * hh.z + a.w * hh.w;
        }
        out[(size_t)(b0g + b) * C_DIM + c] = s;
    }
}

// ---------------------------------------------------------------------------
// kernel_launch: graph-capturable, allocation-free
// Inputs: x, W_hx, W_hh, b_h, W_ph, b_p
// ---------------------------------------------------------------------------
extern "C" void kernel_launch(void* const* d_in, const int* in_sizes, int n_in,
                              void* d_out, int out_size) {
    const float* x    = (const float*)d_in[0];
    const float* W_hx = (const float*)d_in[1];
    const float* W_hh = (const float*)d_in[2];
    const float* b_h  = (const float*)d_in[3];
    const float* W_ph = (const float*)d_in[4];
    const float* b_p  = (const float*)d_in[5];
    float* out = (float*)d_out;

    cudaFuncSetAttribute(rnn_mma_kernel, cudaFuncAttributeMaxDynamicSharedMemorySize, SM_TOTAL);
    rnn_mma_kernel<<<NCTA, 256, SM_TOTAL>>>(x, W_hx, W_hh, b_h, W_ph, b_p, out);
}